// round 5
// baseline (speedup 1.0000x reference)
#include <cuda_runtime.h>

#define DT 0.005f

// ---------------- scratch (no allocation allowed) ----------------
__device__ float    g_partials[4096];
__device__ unsigned g_sem = 0;
__device__ float4   g_coef[8192];   // fallback path only

// fallback float2 swizzle
__device__ __forceinline__ int swz(int t)  { return t ^ ((t >> 4) & 15); }
// float4 swizzle: XOR low 3 bits with bits [3:6) -> stride-8 halo reads spread
__device__ __forceinline__ int swz4(int s) { return s ^ ((s >> 3) & 7); }

__device__ __forceinline__ void cp16(unsigned dst, const void* src) {
    asm volatile("cp.async.cg.shared.global [%0], [%1], 16;\n" :: "r"(dst), "l"(src));
}
__device__ __forceinline__ void cp_commit() { asm volatile("cp.async.commit_group;\n"); }
template <int N>
__device__ __forceinline__ void cp_wait() { asm volatile("cp.async.wait_group %0;\n" :: "n"(N)); }

// ============================================================================
// Scan-free half-row kernel. T=4096 split as 2 CTAs x 2048 steps; 128 thr x
// CHUNK=16. Entry state via 64-step halo warm-up (g^64 ~ 2e-10 << fp32 eps,
// tolerance 1e-3): NO block scan, ONE __syncthreads, loss fused into emit.
//   - smem: pred pairs for [tbase-64, tbase+2048), XOR-swizzled float4
//   - steady threads: kv*, kp* constants; transient (t<160, first CTA of row
//     only) threads replay exactly from t=0 with a 96-entry gain table
//   - grid 2B=1024 -> ~7 CTAs/SM needed, 8 resident -> single wave
// ============================================================================
__global__ void __launch_bounds__(128, 8)
kf_half(const float* __restrict__ pred, const float* __restrict__ targ,
        const float* __restrict__ qv_p, const float* __restrict__ r_p,
        float* __restrict__ out, int B)
{
    constexpr int NT    = 128;
    constexpr int CHUNK = 16;
    constexpr int HTIME = NT * CHUNK;    // 2048 timesteps per CTA
    constexpr int HALO  = 64;            // warm-up length (timesteps)
    constexpr int NPREF = HALO / 2;      // 32 halo float4 pairs
    constexpr int NPAIR = HTIME / 2;     // 1024 main pairs
    constexpr int TTR   = 96;            // transient gain length

    __shared__ float4 sz4[NPAIR + NPREF];   // [0,32) halo, [32,1056) main
    __shared__ float4 s_tc[TTR];            // transient (g, kv, u, inv)
    __shared__ float4 s_st;                 // (g*, kv*, u*, inv*)
    __shared__ float  s_kps;                // kp* = u*/kv*
    __shared__ float  sred[4];
    __shared__ float  sf[128];
    __shared__ int    s_last;

    const int j    = threadIdx.x;
    const int blk  = blockIdx.x;
    const int row  = blk >> 1;
    const int half = blk & 1;
    const int lane = j & 31;
    const int wrp  = j >> 5;

    const float qv = *qv_p;
    const float r  = *r_p;

    const unsigned sa = (unsigned)__cvta_generic_to_shared(sz4);

    // ---- async stage: pred pairs for this half (+halo prefix for half 1) ----
    const float4* gp4 = (const float4*)pred + (size_t)row * 2048;
    if (half == 0) {
        #pragma unroll
        for (int k = 0; k < 8; ++k) {
            int m = j + k * NT;
            cp16(sa + 16u * (unsigned)swz4(m + NPREF), gp4 + m);
        }
    } else {
        const float4* gh = gp4 + (NPAIR - NPREF);   // pair 992 = t 1984
        #pragma unroll
        for (int k = 0; k < 8; ++k) {
            int m = j + k * NT;
            cp16(sa + 16u * (unsigned)swz4(m), gh + m);
        }
        if (j < NPREF) cp16(sa + 16u * (unsigned)swz4(NPAIR + j), gh + NPAIR + j);
    }
    cp_commit();

    // ---- steady-state gains (thread 0; overlaps staging) ----
    if (j == 0) {
        float cstar = 0.5f * (sqrtf(fmaf(qv, qv, 4.f * r * qv)) - qv);
        float cps   = cstar + qv;
        float Ss    = cps + r;
        float invs  = 1.0f / Ss;
        float kvs   = cps * invs;
        float us    = DT * cstar * invs;
        s_st  = make_float4(1.0f - kvs, kvs, us, invs);
        s_kps = us / kvs;                 // kp* = u*/(1-g*) , 1-g* = kv*
    }

    // ---- transient gain table (first CTA of each row only) ----
    if (half == 0 && j < TTR / CHUNK) {
        const float r64   = 64.f * r;
        const float rqv64 = 64.f * r * qv;
        const float qvr   = qv + r;
        const float qvr64 = 64.f * qvr;
        const int tstart  = j * CHUNK;
        float p = 1.f, q = 1.f;                       // c0 = 1
        for (int s = 0; s < tstart; ++s) {
            float pn = fmaf(r64, p, rqv64 * q);
            float qn = fmaf(qvr64, q, 64.f * p);
            p = pn; q = qn;
        }
        #pragma unroll
        for (int i = 0; i < CHUNK; ++i) {
            float num  = fmaf(qv,  q, p);
            float den  = fmaf(qvr, q, p);
            float invd = 1.0f / den;
            float kv   = num * invd;
            float inv  = q * invd;
            float u    = DT * p * invd;
            s_tc[tstart + i] = make_float4(1.0f - kv, kv, u, inv);
            float pn = fmaf(r64, p, rqv64 * q);
            float qn = fmaf(qvr64, q, 64.f * p);
            p = pn; q = qn;
        }
    }

    cp_wait<0>();
    __syncthreads();                     // the ONLY full-block phase barrier

    const float4 st  = s_st;             // (g*, kv*, u*, inv*)
    const float  kps = s_kps;
    const int    t0g = half * HTIME + j * CHUNK;   // global chunk start
    float acc = 0.f;

    if (half == 0 && t0g < TTR + HALO) {
        // ---- exact path (j < 10 of first CTA): replay from t = 0 ----
        const float2* gt2 = (const float2*)(targ + (size_t)row * 8192);
        const int t0 = t0g;
        float vx = 0.f, vy = 0.f, b = 0.f;
        for (int t = 0; t < t0 + CHUNK; ++t) {
            float4 cf = (t < TTR) ? s_tc[t] : st;
            float4 Z  = sz4[swz4(NPREF + (t >> 1))];
            float zx = (t & 1) ? Z.z : Z.x;
            float zy = (t & 1) ? Z.w : Z.y;
            float kp = fmaf(b, cf.w, cf.z);
            b = r * kp;
            float dx = zx - vx, dy = zy - vy;
            if (t >= t0 && t > 0) {
                float2 w = gt2[t];
                float ex = fmaf(-DT, w.x, fmaf(kp, dx, DT * vx));
                float ey = fmaf(-DT, w.y, fmaf(kp, dy, DT * vy));
                acc = fmaf(ex, ex, fmaf(ey, ey, acc));
            }
            vx = fmaf(cf.y, dx, vx);
            vy = fmaf(cf.y, dy, vy);
        }
    } else {
        // ---- steady path: 64-step halo warm-up, then fused emit+loss ----
        const float kv = st.y;
        const int   ph = 8 * j;          // halo start pair (local)
        float vx = 0.f, vy = 0.f;
        #pragma unroll
        for (int i = 0; i < NPREF; ++i) {
            float4 Z = sz4[swz4(ph + i)];
            vx = fmaf(kv, Z.x - vx, vx);
            vy = fmaf(kv, Z.y - vy, vy);
            vx = fmaf(kv, Z.z - vx, vx);
            vy = fmaf(kv, Z.w - vy, vy);
        }
        const float4* gt = (const float4*)targ + (size_t)row * 2048
                         + (size_t)half * NPAIR + 8 * j;
        float4 w = gt[0];
        #pragma unroll
        for (int i = 0; i < 8; ++i) {
            float4 wn;
            if (i < 7) wn = gt[i + 1];
            float4 Z = sz4[swz4(ph + NPREF + i)];
            float dx0 = Z.x - vx, dy0 = Z.y - vy;
            float ex0 = fmaf(-DT, w.x, fmaf(kps, dx0, DT * vx));
            float ey0 = fmaf(-DT, w.y, fmaf(kps, dy0, DT * vy));
            acc = fmaf(ex0, ex0, fmaf(ey0, ey0, acc));
            vx = fmaf(kv, dx0, vx);
            vy = fmaf(kv, dy0, vy);
            float dx1 = Z.z - vx, dy1 = Z.w - vy;
            float ex1 = fmaf(-DT, w.z, fmaf(kps, dx1, DT * vx));
            float ey1 = fmaf(-DT, w.w, fmaf(kps, dy1, DT * vy));
            acc = fmaf(ex1, ex1, fmaf(ey1, ey1, acc));
            vx = fmaf(kv, dx1, vx);
            vy = fmaf(kv, dy1, vy);
            w = wn;
        }
    }

    // ---- block reduce (4 warps) -> partial ----
    #pragma unroll
    for (int o = 16; o; o >>= 1) acc += __shfl_down_sync(0xffffffffu, acc, o);
    if (lane == 0) sred[wrp] = acc;
    __syncthreads();
    if (j == 0) {
        float v = sred[0] + sred[1] + sred[2] + sred[3];
        g_partials[blk] = v;
        __threadfence();
        unsigned done = atomicAdd(&g_sem, 1u);
        s_last = (done == (unsigned)gridDim.x - 1u);
    }
    __syncthreads();

    // ---- last CTA: deterministic final reduction + semaphore reset ----
    if (s_last) {
        __threadfence();
        const int nblk = 2 * B;
        float v = 0.f;
        for (int i = j; i < nblk; i += NT) v += g_partials[i];
        sf[j] = v;
        __syncthreads();
        for (int o = 64; o; o >>= 1) {
            if (j < o) sf[j] += sf[j + o];
            __syncthreads();
        }
        if (j == 0) {
            out[0] = sf[0] / ((float)B * 4095.0f * 2.f);
            atomicExch(&g_sem, 0u);
        }
    }
}

// ============================================================================
// Fallback path (any T) — proven Round-1 kernels
// ============================================================================
__global__ void kf_setup(const float* __restrict__ q_vel_p,
                         const float* __restrict__ r_vel_p, int T) {
    __shared__ float skp[4096];
    __shared__ float skv[4096];
    __shared__ int   s_conv;
    __shared__ float s_kp_last, s_kv_last;

    int Tser = T < 4096 ? T : 4096;
    if (threadIdx.x == 0) {
        float qvv = *q_vel_p;
        float rr  = *r_vel_p;
        float bb = 0.f, cc = 1.f;
        float kp = 0.f, kv = 0.f;
        int tconv = Tser;
        for (int t = 0; t < Tser; ++t) {
            float cp  = cc + qvv;
            float bp  = fmaf(DT, cc, bb);
            float S   = cp + rr;
            float inv = __fdividef(1.f, S);
            kv = cp * inv;
            kp = bp * inv;
            skp[t] = kp; skv[t] = kv;
            float rs = rr * inv;
            float nc = cp * rs;
            float nb = bp * rs;
            if (nc == cc && nb == bb) { tconv = t + 1; break; }
            cc = nc; bb = nb;
        }
        s_conv = tconv; s_kp_last = kp; s_kv_last = kv;
    }
    __syncthreads();
    int   tconv = s_conv;
    float kpl = s_kp_last, kvl = s_kv_last;
    for (int t = threadIdx.x; t < T; t += blockDim.x) {
        float kp = (t < tconv) ? skp[t] : kpl;
        float kv = (t < tconv) ? skv[t] : kvl;
        g_coef[t] = make_float4(1.f - kv, kv, DT - kp, kp);
    }
}

__global__ void __launch_bounds__(256)
kf_main(const float* __restrict__ pred, const float* __restrict__ targ, int T) {
    extern __shared__ float2 sp2[];
    const int NT = 256;
    int j = threadIdx.x, bb = blockIdx.x;

    const float4* gp = (const float4*)(pred + (size_t)bb * T * 2);
    int n4 = (T * 2) / 4;
    for (int m = j; m < n4; m += NT) {
        float4 v = gp[m];
        sp2[swz(2 * m)]     = make_float2(v.x, v.y);
        sp2[swz(2 * m + 1)] = make_float2(v.z, v.w);
    }
    __syncthreads();

    int chunk = (T + NT - 1) / NT;
    int t0 = j * chunk;

    float A = 1.f, Bx = 0.f, By = 0.f;
    for (int i = 0; i < chunk; ++i) {
        int t = t0 + i;
        if (t >= T) break;
        float4 cf = g_coef[t];
        float2 z  = sp2[swz(t)];
        A  = A * cf.x;
        Bx = fmaf(cf.x, Bx, cf.y * z.x);
        By = fmaf(cf.x, By, cf.y * z.y);
    }

    __shared__ float sA[256], sBx[256], sBy[256];
    sA[j] = A; sBx[j] = Bx; sBy[j] = By;
    __syncthreads();
    for (int off = 1; off < NT; off <<= 1) {
        float a2 = 0.f, bx2 = 0.f, by2 = 0.f;
        bool act = (j >= off);
        if (act) {
            float ap = sA[j - off], bxp = sBx[j - off], byp = sBy[j - off];
            a2  = A * ap;
            bx2 = fmaf(A, bxp, Bx);
            by2 = fmaf(A, byp, By);
        }
        __syncthreads();
        if (act) { A = a2; Bx = bx2; By = by2; sA[j] = A; sBx[j] = Bx; sBy[j] = By; }
        __syncthreads();
    }
    float vx = (j == 0) ? 0.f : sBx[j - 1];
    float vy = (j == 0) ? 0.f : sBy[j - 1];

    const float2* gt2 = (const float2*)(targ + (size_t)bb * T * 2);
    float acc = 0.f;
    for (int i = 0; i < chunk; ++i) {
        int t = t0 + i;
        if (t >= T) break;
        float4 cf = g_coef[t];
        float2 z  = sp2[swz(t)];
        if (t > 0) {
            float2 w = gt2[t];
            float ex = fmaf(cf.z, vx, fmaf(cf.w, z.x, -DT * w.x));
            float ey = fmaf(cf.z, vy, fmaf(cf.w, z.y, -DT * w.y));
            acc = fmaf(ex, ex, fmaf(ey, ey, acc));
        }
        vx = fmaf(cf.x, vx, cf.y * z.x);
        vy = fmaf(cf.x, vy, cf.y * z.y);
    }

    for (int o = 16; o; o >>= 1) acc += __shfl_down_sync(0xffffffffu, acc, o);
    __shared__ float swsum[8];
    if ((j & 31) == 0) swsum[j >> 5] = acc;
    __syncthreads();
    if (j < 8) {
        float v = swsum[j];
        v += __shfl_down_sync(0xffu, v, 4);
        v += __shfl_down_sync(0xffu, v, 2);
        v += __shfl_down_sync(0xffu, v, 1);
        if (j == 0) g_partials[bb] = v;
    }
}

__global__ void kf_reduce(float* __restrict__ out, int B, int T) {
    __shared__ float s[256];
    float v = 0.f;
    for (int i = threadIdx.x; i < B; i += blockDim.x) v += g_partials[i];
    s[threadIdx.x] = v;
    __syncthreads();
    for (int o = 128; o; o >>= 1) {
        if (threadIdx.x < o) s[threadIdx.x] += s[threadIdx.x + o];
        __syncthreads();
    }
    if (threadIdx.x == 0)
        out[0] = s[0] / ((float)B * (float)(T - 1) * 2.f);
}

extern "C" void kernel_launch(void* const* d_in, const int* in_sizes, int n_in,
                              void* d_out, int out_size) {
    // metadata order: pred_vel, targ_vel, q_pos, q_vel, r_vel, p0
    const float* pred  = (const float*)d_in[0];
    const float* targ  = (const float*)d_in[1];
    const float* q_vel = (const float*)d_in[3];
    const float* r_vel = (const float*)d_in[4];
    int B = in_sizes[5] / 2;          // p0 is (B, 2)
    int T = in_sizes[0] / (B * 2);    // pred_vel is (B, T, 2)

    if (T == 4096 && B >= 1 && B <= 2048) {
        kf_half<<<2 * B, 128>>>(pred, targ, q_vel, r_vel, (float*)d_out, B);
    } else {
        kf_setup<<<1, 256>>>(q_vel, r_vel, T);
        size_t sh = (size_t)T * sizeof(float2);
        kf_main<<<B, 256, sh>>>(pred, targ, T);
        kf_reduce<<<1, 256>>>((float*)d_out, B, T);
    }
}

// round 6
// speedup vs baseline: 1.8221x; 1.8221x over previous
#include <cuda_runtime.h>

#define DT 0.005f

// ---------------- scratch (no allocation allowed) ----------------
__device__ float    g_partials[4096];
__device__ unsigned g_sem = 0;
__device__ float4   g_coef[8192];   // fallback path only

// fallback float2 swizzle
__device__ __forceinline__ int swz(int t)  { return t ^ ((t >> 4) & 15); }
// float4 swizzle
__device__ __forceinline__ int swz4(int s) { return s ^ ((s >> 3) & 7); }

__device__ __forceinline__ void cp16(unsigned dst, const void* src) {
    asm volatile("cp.async.cg.shared.global [%0], [%1], 16;\n" :: "r"(dst), "l"(src));
}
__device__ __forceinline__ void cp_commit() { asm volatile("cp.async.commit_group;\n"); }
template <int N>
__device__ __forceinline__ void cp_wait() { asm volatile("cp.async.wait_group %0;\n" :: "n"(N)); }

// ============================================================================
// Split-row scan kernel. T=4096 as 2 CTAs x 2048 steps, 128 thr x CHUNK=16.
//  - CTA-entry state via PARALLEL halo dot product (64 steps, exp2f weights,
//    g^64 ~ 2e-10 << 1e-3 tol) -- no serial warm-up, 3% extra traffic
//  - 3-component block scan (G, Bx, By); b is data-independent:
//    steady kp* const; transient entry-b from 6 precomputed (Gb,Hb) pairs
//  - pass2 writes windowed pred part P in place; pass3 coalesced targ
//  - grid 2B = 1024 @ <=8 CTAs/SM -> single wave, 2x concurrency vs R3
// ============================================================================
__global__ void __launch_bounds__(128, 8)
kf_split(const float* __restrict__ pred, const float* __restrict__ targ,
         const float* __restrict__ qv_p, const float* __restrict__ r_p,
         float* __restrict__ out, int B)
{
    constexpr int NT    = 128;
    constexpr int CHUNK = 16;
    constexpr int NPREF = 32;            // halo pairs (64 timesteps)
    constexpr int NPAIR = 1024;          // main pairs (2048 timesteps)
    constexpr int TTR   = 96;            // transient gain length
    constexpr int NTC   = TTR / CHUNK;   // 6 transient chunks/threads

    __shared__ float4 sz4[NPAIR + NPREF];   // [0,32) halo, [32,1056) main
    __shared__ float4 s_tc[TTR];            // transient (g, kv, u, inv)
    __shared__ float2 s_tb[NTC];            // per-chunk b-affine (Gb, Hb)
    __shared__ float4 s_st;                 // (g*, kv*, u*, inv*)
    __shared__ float2 s_c2;                 // (kp*, g*^16)
    __shared__ float2 s_vinit;              // halo-derived CTA entry v
    __shared__ float  sWG[4], sWBx[4], sWBy[4];
    __shared__ float  sred[4];
    __shared__ float  sf[128];
    __shared__ int    s_last;

    const int j    = threadIdx.x;
    const int blk  = blockIdx.x;
    const int row  = blk >> 1;
    const int half = blk & 1;
    const int lane = j & 31;
    const int wrp  = j >> 5;

    const float qv = *qv_p;
    const float r  = *r_p;

    const unsigned sa = (unsigned)__cvta_generic_to_shared(sz4);

    // ---- async stage: pred pairs (+ halo prefix for half 1) ----
    // local pair lp in [0,1056): global pair = (half ? 992 : -32) + lp
    const float4* gp4 = (const float4*)pred + (size_t)row * 2048;
    if (half == 0) {
        #pragma unroll
        for (int k = 0; k < 8; ++k) {
            int m = j + k * NT;                     // main pair index
            cp16(sa + 16u * (unsigned)swz4(m + NPREF), gp4 + m);
        }
    } else {
        const float4* gh = gp4 + (NPAIR - NPREF);   // global pair 992
        #pragma unroll
        for (int k = 0; k < 8; ++k) {
            int lp = j + k * NT;
            cp16(sa + 16u * (unsigned)swz4(lp), gh + lp);
        }
        if (j < NPREF) cp16(sa + 16u * (unsigned)swz4(NPAIR + j), gh + NPAIR + j);
    }
    cp_commit();

    // ---- steady-state gains (thread 0; overlaps staging) ----
    if (j == 0) {
        float cstar = 0.5f * (sqrtf(fmaf(qv, qv, 4.f * r * qv)) - qv);
        float cps   = cstar + qv;
        float Ss    = cps + r;
        float invs  = 1.0f / Ss;
        float kvs   = cps * invs;
        float gs    = 1.0f - kvs;
        float us    = DT * cstar * invs;
        s_st = make_float4(gs, kvs, us, invs);
        float g2 = gs * gs, g4 = g2 * g2, g8 = g4 * g4;
        s_c2 = make_float2(us / kvs, g8 * g8);   // (kp*, g^16)
        if (half == 0) s_vinit = make_float2(0.f, 0.f);
    }

    // ---- transient gain table + per-chunk b-affine (half 0, j<6) ----
    if (half == 0 && j < NTC) {
        const float r64   = 64.f * r;
        const float rqv64 = 64.f * r * qv;
        const float qvr   = qv + r;
        const float qvr64 = 64.f * qvr;
        const int tstart  = j * CHUNK;
        float p = 1.f, q = 1.f;                       // c0 = 1
        for (int s = 0; s < tstart; ++s) {
            float pn = fmaf(r64, p, rqv64 * q);
            float qn = fmaf(qvr64, q, 64.f * p);
            p = pn; q = qn;
        }
        float Gb = 1.f, Hb = 0.f;                     // b' = g*b + r*u
        #pragma unroll
        for (int i = 0; i < CHUNK; ++i) {
            float num  = fmaf(qv,  q, p);
            float den  = fmaf(qvr, q, p);
            float invd = 1.0f / den;
            float kv   = num * invd;
            float inv  = q * invd;
            float u    = DT * p * invd;
            float g    = 1.0f - kv;
            s_tc[tstart + i] = make_float4(g, kv, u, inv);
            Hb = fmaf(g, Hb, r * u);
            Gb *= g;
            float pn = fmaf(r64, p, rqv64 * q);
            float qn = fmaf(qvr64, q, 64.f * p);
            p = pn; q = qn;
        }
        s_tb[j] = make_float2(Gb, Hb);
    }

    cp_wait<0>();
    __syncthreads();                         // [A] data + tables ready

    const float4 st  = s_st;                 // (g*, kv*, u*, inv*)
    const float  kps = s_c2.x;
    const float  g16 = s_c2.y;
    const bool   trans = (half == 0) && (j < NTC);
    const int    p0  = NPREF + 8 * j;        // first local pair of my chunk

    // ---- half 1: parallel halo dot product on warp 0 ----
    if (half == 1 && wrp == 0) {
        // v_init = kv * sum_{s=0..63} g^(63-s) z_s ; lane handles pair `lane`
        float lg = log2f(st.x);
        float e0 = (float)(63 - 2 * lane);
        float w0 = st.y * exp2f(e0 * lg);
        float w1 = st.y * exp2f((e0 - 1.f) * lg);
        float4 Z = sz4[swz4(lane)];
        float hx = fmaf(w0, Z.x, w1 * Z.z);
        float hy = fmaf(w0, Z.y, w1 * Z.w);
        #pragma unroll
        for (int o = 16; o; o >>= 1) {
            hx += __shfl_down_sync(0xffffffffu, hx, o);
            hy += __shfl_down_sync(0xffffffffu, hy, o);
        }
        if (lane == 0) s_vinit = make_float2(hx, hy);
    }

    // ---- pass 1: local v-affine over my chunk ----
    float G, Bx = 0.f, By = 0.f;
    if (trans) {
        G = 1.f;
        const int t0 = j * CHUNK;
        #pragma unroll
        for (int i = 0; i < 8; ++i) {
            float4 Z  = sz4[swz4(p0 + i)];
            float4 c0 = s_tc[t0 + 2 * i];
            float4 c1 = s_tc[t0 + 2 * i + 1];
            Bx = fmaf(c0.x, Bx, c0.y * Z.x);
            By = fmaf(c0.x, By, c0.y * Z.y);
            Bx = fmaf(c1.x, Bx, c1.y * Z.z);
            By = fmaf(c1.x, By, c1.y * Z.w);
            G *= c0.x * c1.x;
        }
    } else {
        const float g = st.x, kv = st.y;
        G = g16;
        #pragma unroll
        for (int i = 0; i < 8; ++i) {
            float4 Z = sz4[swz4(p0 + i)];
            Bx = fmaf(g, Bx, kv * Z.x);
            By = fmaf(g, By, kv * Z.y);
            Bx = fmaf(g, Bx, kv * Z.z);
            By = fmaf(g, By, kv * Z.w);
        }
    }

    // ---- 3-component scan: intra-warp inclusive + per-thread warp fold ----
    #pragma unroll
    for (int off = 1; off < 32; off <<= 1) {
        float pG  = __shfl_up_sync(0xffffffffu, G,  off);
        float pBx = __shfl_up_sync(0xffffffffu, Bx, off);
        float pBy = __shfl_up_sync(0xffffffffu, By, off);
        if (lane >= off) {
            Bx = fmaf(G, pBx, Bx);
            By = fmaf(G, pBy, By);
            G *= pG;
        }
    }
    float eG  = __shfl_up_sync(0xffffffffu, G,  1);
    float eBx = __shfl_up_sync(0xffffffffu, Bx, 1);
    float eBy = __shfl_up_sync(0xffffffffu, By, 1);
    if (lane == 0) { eG = 1.f; eBx = 0.f; eBy = 0.f; }
    if (lane == 31) { sWG[wrp] = G; sWBx[wrp] = Bx; sWBy[wrp] = By; }
    __syncthreads();                         // [B] warp partials + v_init ready

    // fold previous warps' partials (<=3) then own exclusive
    float Gp = 1.f, Bpx = 0.f, Bpy = 0.f;
    #pragma unroll
    for (int k = 0; k < 3; ++k) {
        if (k < wrp) {
            Bpx = fmaf(sWG[k], Bpx, sWBx[k]);
            Bpy = fmaf(sWG[k], Bpy, sWBy[k]);
            Gp *= sWG[k];
        }
    }
    float Ge  = eG * Gp;
    float Bex = fmaf(eG, Bpx, eBx);
    float Bey = fmaf(eG, Bpy, eBy);
    float2 vi = s_vinit;
    float vx = fmaf(Ge, vi.x, Bex);          // v at chunk entry
    float vy = fmaf(Ge, vi.y, Bey);

    // entry b: steady threads converged to b*; transient folds (Gb,Hb) pairs
    float b;
    if (trans) {
        b = 0.f;
        #pragma unroll
        for (int k = 0; k < NTC - 1; ++k) {
            if (k < j) { float2 tb = s_tb[k]; b = fmaf(tb.x, b, tb.y); }
        }
    } else {
        b = r * kps;                          // b* (unused in steady pass2)
    }

    // ---- pass 2: replay, overwrite pred pairs with windowed P pairs ----
    if (trans) {
        const int t0 = j * CHUNK;
        #pragma unroll
        for (int i = 0; i < 8; ++i) {
            float4 Z  = sz4[swz4(p0 + i)];
            float4 c0 = s_tc[t0 + 2 * i];
            float4 c1 = s_tc[t0 + 2 * i + 1];
            float kp0 = fmaf(b, c0.w, c0.z);  b = r * kp0;
            float dx0 = Z.x - vx, dy0 = Z.y - vy;
            float Px0 = fmaf(kp0, dx0, DT * vx);
            float Py0 = fmaf(kp0, dy0, DT * vy);
            vx = fmaf(c0.y, dx0, vx); vy = fmaf(c0.y, dy0, vy);
            float kp1 = fmaf(b, c1.w, c1.z);  b = r * kp1;
            float dx1 = Z.z - vx, dy1 = Z.w - vy;
            float Px1 = fmaf(kp1, dx1, DT * vx);
            float Py1 = fmaf(kp1, dy1, DT * vy);
            vx = fmaf(c1.y, dx1, vx); vy = fmaf(c1.y, dy1, vy);
            sz4[swz4(p0 + i)] = make_float4(Px0, Py0, Px1, Py1);
        }
    } else {
        const float kv = st.y;
        #pragma unroll
        for (int i = 0; i < 8; ++i) {
            float4 Z = sz4[swz4(p0 + i)];
            float dx0 = Z.x - vx, dy0 = Z.y - vy;
            float Px0 = fmaf(kps, dx0, DT * vx);
            float Py0 = fmaf(kps, dy0, DT * vy);
            vx = fmaf(kv, dx0, vx); vy = fmaf(kv, dy0, vy);
            float dx1 = Z.z - vx, dy1 = Z.w - vy;
            float Px1 = fmaf(kps, dx1, DT * vx);
            float Py1 = fmaf(kps, dy1, DT * vy);
            vx = fmaf(kv, dx1, vx); vy = fmaf(kv, dy1, vy);
            sz4[swz4(p0 + i)] = make_float4(Px0, Py0, Px1, Py1);
        }
    }
    __syncthreads();                         // [C] P ready

    // ---- pass 3: coalesced targ + loss ----
    const float4* gt = (const float4*)targ + (size_t)row * 2048
                     + (size_t)half * NPAIR;
    float acc = 0.f;
    #pragma unroll
    for (int k = 0; k < 8; ++k) {
        int m = j + k * NT;
        float4 w = gt[m];
        float4 P = sz4[swz4(NPREF + m)];
        if (half != 0 || m != 0) {           // t = 0 has no loss term
            float ex = fmaf(-DT, w.x, P.x);
            float ey = fmaf(-DT, w.y, P.y);
            acc = fmaf(ex, ex, fmaf(ey, ey, acc));
        }
        float ex1 = fmaf(-DT, w.z, P.z);
        float ey1 = fmaf(-DT, w.w, P.w);
        acc = fmaf(ex1, ex1, fmaf(ey1, ey1, acc));
    }

    // ---- block reduce -> partial ----
    #pragma unroll
    for (int o = 16; o; o >>= 1) acc += __shfl_down_sync(0xffffffffu, acc, o);
    if (lane == 0) sred[wrp] = acc;
    __syncthreads();
    if (j == 0) {
        float v = sred[0] + sred[1] + sred[2] + sred[3];
        g_partials[blk] = v;
        __threadfence();
        unsigned done = atomicAdd(&g_sem, 1u);
        s_last = (done == (unsigned)gridDim.x - 1u);
    }
    __syncthreads();

    // ---- last CTA: deterministic final reduction + semaphore reset ----
    if (s_last) {
        __threadfence();
        const int nblk = 2 * B;
        float v = 0.f;
        for (int i = j; i < nblk; i += NT) v += g_partials[i];
        sf[j] = v;
        __syncthreads();
        for (int o = 64; o; o >>= 1) {
            if (j < o) sf[j] += sf[j + o];
            __syncthreads();
        }
        if (j == 0) {
            out[0] = sf[0] / ((float)B * 4095.0f * 2.f);
            atomicExch(&g_sem, 0u);
        }
    }
}

// ============================================================================
// Fallback path (any T) — proven Round-1 kernels
// ============================================================================
__global__ void kf_setup(const float* __restrict__ q_vel_p,
                         const float* __restrict__ r_vel_p, int T) {
    __shared__ float skp[4096];
    __shared__ float skv[4096];
    __shared__ int   s_conv;
    __shared__ float s_kp_last, s_kv_last;

    int Tser = T < 4096 ? T : 4096;
    if (threadIdx.x == 0) {
        float qvv = *q_vel_p;
        float rr  = *r_vel_p;
        float bb = 0.f, cc = 1.f;
        float kp = 0.f, kv = 0.f;
        int tconv = Tser;
        for (int t = 0; t < Tser; ++t) {
            float cp  = cc + qvv;
            float bp  = fmaf(DT, cc, bb);
            float S   = cp + rr;
            float inv = __fdividef(1.f, S);
            kv = cp * inv;
            kp = bp * inv;
            skp[t] = kp; skv[t] = kv;
            float rs = rr * inv;
            float nc = cp * rs;
            float nb = bp * rs;
            if (nc == cc && nb == bb) { tconv = t + 1; break; }
            cc = nc; bb = nb;
        }
        s_conv = tconv; s_kp_last = kp; s_kv_last = kv;
    }
    __syncthreads();
    int   tconv = s_conv;
    float kpl = s_kp_last, kvl = s_kv_last;
    for (int t = threadIdx.x; t < T; t += blockDim.x) {
        float kp = (t < tconv) ? skp[t] : kpl;
        float kv = (t < tconv) ? skv[t] : kvl;
        g_coef[t] = make_float4(1.f - kv, kv, DT - kp, kp);
    }
}

__global__ void __launch_bounds__(256)
kf_main(const float* __restrict__ pred, const float* __restrict__ targ, int T) {
    extern __shared__ float2 sp2[];
    const int NT = 256;
    int j = threadIdx.x, bb = blockIdx.x;

    const float4* gp = (const float4*)(pred + (size_t)bb * T * 2);
    int n4 = (T * 2) / 4;
    for (int m = j; m < n4; m += NT) {
        float4 v = gp[m];
        sp2[swz(2 * m)]     = make_float2(v.x, v.y);
        sp2[swz(2 * m + 1)] = make_float2(v.z, v.w);
    }
    __syncthreads();

    int chunk = (T + NT - 1) / NT;
    int t0 = j * chunk;

    float A = 1.f, Bx = 0.f, By = 0.f;
    for (int i = 0; i < chunk; ++i) {
        int t = t0 + i;
        if (t >= T) break;
        float4 cf = g_coef[t];
        float2 z  = sp2[swz(t)];
        A  = A * cf.x;
        Bx = fmaf(cf.x, Bx, cf.y * z.x);
        By = fmaf(cf.x, By, cf.y * z.y);
    }

    __shared__ float sA[256], sBx[256], sBy[256];
    sA[j] = A; sBx[j] = Bx; sBy[j] = By;
    __syncthreads();
    for (int off = 1; off < NT; off <<= 1) {
        float a2 = 0.f, bx2 = 0.f, by2 = 0.f;
        bool act = (j >= off);
        if (act) {
            float ap = sA[j - off], bxp = sBx[j - off], byp = sBy[j - off];
            a2  = A * ap;
            bx2 = fmaf(A, bxp, Bx);
            by2 = fmaf(A, byp, By);
        }
        __syncthreads();
        if (act) { A = a2; Bx = bx2; By = by2; sA[j] = A; sBx[j] = Bx; sBy[j] = By; }
        __syncthreads();
    }
    float vx = (j == 0) ? 0.f : sBx[j - 1];
    float vy = (j == 0) ? 0.f : sBy[j - 1];

    const float2* gt2 = (const float2*)(targ + (size_t)bb * T * 2);
    float acc = 0.f;
    for (int i = 0; i < chunk; ++i) {
        int t = t0 + i;
        if (t >= T) break;
        float4 cf = g_coef[t];
        float2 z  = sp2[swz(t)];
        if (t > 0) {
            float2 w = gt2[t];
            float ex = fmaf(cf.z, vx, fmaf(cf.w, z.x, -DT * w.x));
            float ey = fmaf(cf.z, vy, fmaf(cf.w, z.y, -DT * w.y));
            acc = fmaf(ex, ex, fmaf(ey, ey, acc));
        }
        vx = fmaf(cf.x, vx, cf.y * z.x);
        vy = fmaf(cf.x, vy, cf.y * z.y);
    }

    for (int o = 16; o; o >>= 1) acc += __shfl_down_sync(0xffffffffu, acc, o);
    __shared__ float swsum[8];
    if ((j & 31) == 0) swsum[j >> 5] = acc;
    __syncthreads();
    if (j < 8) {
        float v = swsum[j];
        v += __shfl_down_sync(0xffu, v, 4);
        v += __shfl_down_sync(0xffu, v, 2);
        v += __shfl_down_sync(0xffu, v, 1);
        if (j == 0) g_partials[bb] = v;
    }
}

__global__ void kf_reduce(float* __restrict__ out, int B, int T) {
    __shared__ float s[256];
    float v = 0.f;
    for (int i = threadIdx.x; i < B; i += blockDim.x) v += g_partials[i];
    s[threadIdx.x] = v;
    __syncthreads();
    for (int o = 128; o; o >>= 1) {
        if (threadIdx.x < o) s[threadIdx.x] += s[threadIdx.x + o];
        __syncthreads();
    }
    if (threadIdx.x == 0)
        out[0] = s[0] / ((float)B * (float)(T - 1) * 2.f);
}

extern "C" void kernel_launch(void* const* d_in, const int* in_sizes, int n_in,
                              void* d_out, int out_size) {
    // metadata order: pred_vel, targ_vel, q_pos, q_vel, r_vel, p0
    const float* pred  = (const float*)d_in[0];
    const float* targ  = (const float*)d_in[1];
    const float* q_vel = (const float*)d_in[3];
    const float* r_vel = (const float*)d_in[4];
    int B = in_sizes[5] / 2;          // p0 is (B, 2)
    int T = in_sizes[0] / (B * 2);    // pred_vel is (B, T, 2)

    if (T == 4096 && B >= 1 && B <= 2048) {
        kf_split<<<2 * B, 128>>>(pred, targ, q_vel, r_vel, (float*)d_out, B);
    } else {
        kf_setup<<<1, 256>>>(q_vel, r_vel, T);
        size_t sh = (size_t)T * sizeof(float2);
        kf_main<<<B, 256, sh>>>(pred, targ, T);
        kf_reduce<<<1, 256>>>((float*)d_out, B, T);
    }
}